// round 16
// baseline (speedup 1.0000x reference)
#include <cuda_runtime.h>
#include <cuda_bf16.h>
#include <cstdint>
#include <cmath>

// ---------------------------------------------------------------------------
// Problem dims
// ---------------------------------------------------------------------------
static constexpr int kT   = 1024;
static constexpr int kHID = 2048;
static constexpr int kNH  = 32;
static constexpr int kNKV = 4;
static constexpr int kHD  = 128;
static constexpr int kE   = 64;
static constexpr int kK   = 8;
static constexpr int kI   = 768;
static constexpr int kCAP = 256;
static constexpr float kEPS = 1e-6f;

// ---------------------------------------------------------------------------
// Static device scratch (no allocations allowed)
// ---------------------------------------------------------------------------
__device__ float g_hnorm [kT * kHID];
__device__ float g_h2    [kT * kHID];
__device__ float g_qbuf  [kT * kNH  * kHD];
__device__ float g_kbuf  [kT * kNKV * kHD];
__device__ float g_vbuf  [kT * kNKV * kHD];
__device__ float g_qh    [(size_t)kNH * kT * kHD];
__device__ float g_krep  [(size_t)kNH * kT * kHD];
__device__ float g_vrep  [(size_t)kNH * kT * kHD];
__device__ float g_attno [kT * kNH * kHD];
__device__ float g_scores[(size_t)kNH * kT * kT];
__device__ float g_logits[kT * kE];
__device__ float g_topw  [kT * kK];
__device__ int   g_topi  [kT * kK];
__device__ int   g_cnt   [kE];
__device__ int   g_tok   [kE * kCAP];
__device__ int   g_slot  [kT * kK];
__device__ float g_xb    [(size_t)kE * kCAP * kHID];
__device__ float g_gbuf  [(size_t)kE * kCAP * kI];
__device__ float g_ubuf  [(size_t)kE * kCAP * kI];

// ---------------------------------------------------------------------------
// Precision / mma helpers
// ---------------------------------------------------------------------------
__device__ __forceinline__ void split_bf16(float x0, float x1,
                                           uint32_t& hi, uint32_t& lo)
{
    __nv_bfloat16 h0 = __float2bfloat16_rn(x0);
    __nv_bfloat16 h1 = __float2bfloat16_rn(x1);
    float r0 = x0 - __bfloat162float(h0);
    float r1 = x1 - __bfloat162float(h1);
    __nv_bfloat16 l0 = __float2bfloat16_rn(r0);
    __nv_bfloat16 l1 = __float2bfloat16_rn(r1);
    hi = (uint32_t)__bfloat16_as_ushort(h0) | ((uint32_t)__bfloat16_as_ushort(h1) << 16);
    lo = (uint32_t)__bfloat16_as_ushort(l0) | ((uint32_t)__bfloat16_as_ushort(l1) << 16);
}

__device__ __forceinline__ void mma_bf16(float c[4], const uint32_t a[4],
                                         const uint32_t b[2])
{
    asm volatile(
        "mma.sync.aligned.m16n8k16.row.col.f32.bf16.bf16.f32 "
        "{%0,%1,%2,%3}, {%4,%5,%6,%7}, {%8,%9}, {%0,%1,%2,%3};\n"
        : "+f"(c[0]), "+f"(c[1]), "+f"(c[2]), "+f"(c[3])
        : "r"(a[0]), "r"(a[1]), "r"(a[2]), "r"(a[3]), "r"(b[0]), "r"(b[1]));
}

#define LDM4(R0, R1, R2, R3, ADDR)                                            \
    asm volatile(                                                             \
        "ldmatrix.sync.aligned.m8n8.x4.shared.b16 {%0,%1,%2,%3}, [%4];"       \
        : "=r"(R0), "=r"(R1), "=r"(R2), "=r"(R3) : "r"(ADDR));

// ---------------------------------------------------------------------------
// ATTENTION GEMM core: BK=32, double-buffered, K-contiguous smem
// (stride 20 words), ldmatrix fragments. NN B fills the SAME layout via a
// transpose-gather (scalar strided LDG, coalesced across threads) and uses
// the SAME vectorized uint4 stores as TB -> no store bank conflicts.
// Smem: 2 stages x 4 arrays x 128 x 20 words = 81920 B dynamic.
// ---------------------------------------------------------------------------
static constexpr int kStr32   = 20;
static constexpr int kArrW32  = 128 * kStr32;
static constexpr int kStageW32= 4 * kArrW32;
static constexpr int kB32Smem = 2 * kStageW32 * 4;

template <bool TB>
__device__ __forceinline__ void bg3_core(
    const float* __restrict__ A, const float* __restrict__ B,
    float* __restrict__ C, int effM, int K,
    int lda, int ldb, int ldc, int m0, int n0,
    const float* __restrict__ addsrc)
{
    extern __shared__ __align__(16) uint32_t dyn[];

    const int tid  = threadIdx.x;
    const int warp = tid >> 5;
    const int lane = tid & 31;
    const int wm   = (warp & 1) * 64;
    const int wn   = (warp >> 1) * 32;
    const int lg   = lane >> 2;
    const int lt   = lane & 3;

    const int arow = tid >> 1;
    const int ahalf= tid & 1;
    const int acol = ahalf * 16;

    const uint32_t sb = (uint32_t)__cvta_generic_to_shared(dyn);
    const uint32_t aoff =
        (uint32_t)((wm + (lane & 15)) * kStr32 + ((lane >> 4) << 2));
    const uint32_t boff =
        (uint32_t)((wn + (lane & 7) + ((lane & 16) >> 1)) * kStr32 +
                   (((lane >> 3) & 1) << 2));

    float acc[4][4][4];
    #pragma unroll
    for (int i = 0; i < 4; ++i)
        #pragma unroll
        for (int j = 0; j < 4; ++j)
            #pragma unroll
            for (int l = 0; l < 4; ++l) acc[i][j][l] = 0.f;

    float av[16], bv[16];

    #define G3_LOAD_A(k0)                                                     \
        {                                                                     \
            int m = m0 + arow;                                                \
            if (m < effM) {                                                   \
                const float* p = A + (size_t)m * lda + (k0) + acol;           \
                *reinterpret_cast<float4*>(&av[0])  = *reinterpret_cast<const float4*>(p);     \
                *reinterpret_cast<float4*>(&av[4])  = *reinterpret_cast<const float4*>(p + 4); \
                *reinterpret_cast<float4*>(&av[8])  = *reinterpret_cast<const float4*>(p + 8); \
                *reinterpret_cast<float4*>(&av[12]) = *reinterpret_cast<const float4*>(p + 12);\
            } else {                                                          \
                _Pragma("unroll")                                             \
                for (int j = 0; j < 16; ++j) av[j] = 0.f;                     \
            }                                                                 \
        }
    #define G3_STORE_A(st)                                                    \
        {                                                                     \
            uint32_t hw[8], lw[8];                                            \
            _Pragma("unroll")                                                 \
            for (int j = 0; j < 8; ++j)                                       \
                split_bf16(av[2*j], av[2*j+1], hw[j], lw[j]);                 \
            uint32_t* dH = dyn + (st) * kStageW32 + arow * kStr32 + ahalf * 8;\
            uint32_t* dL = dH + kArrW32;                                      \
            *reinterpret_cast<uint4*>(dH)     = make_uint4(hw[0],hw[1],hw[2],hw[3]); \
            *reinterpret_cast<uint4*>(dH + 4) = make_uint4(hw[4],hw[5],hw[6],hw[7]); \
            *reinterpret_cast<uint4*>(dL)     = make_uint4(lw[0],lw[1],lw[2],lw[3]); \
            *reinterpret_cast<uint4*>(dL + 4) = make_uint4(lw[4],lw[5],lw[6],lw[7]); \
        }
    #define G3_LOAD_B(k0)                                                     \
        if (TB) {                                                             \
            const float* p = B + (size_t)(n0 + arow) * ldb + (k0) + acol;     \
            *reinterpret_cast<float4*>(&bv[0])  = *reinterpret_cast<const float4*>(p);     \
            *reinterpret_cast<float4*>(&bv[4])  = *reinterpret_cast<const float4*>(p + 4); \
            *reinterpret_cast<float4*>(&bv[8])  = *reinterpret_cast<const float4*>(p + 8); \
            *reinterpret_cast<float4*>(&bv[12]) = *reinterpret_cast<const float4*>(p + 12);\
        } else {                                                              \
            const float* p = B + (size_t)((k0) + ahalf * 16) * ldb + n0 + arow; \
            _Pragma("unroll")                                                 \
            for (int j = 0; j < 16; ++j) bv[j] = p[(size_t)j * ldb];          \
        }
    #define G3_STORE_B(st)                                                    \
        {                                                                     \
            uint32_t hw[8], lw[8];                                            \
            _Pragma("unroll")                                                 \
            for (int j = 0; j < 8; ++j)                                       \
                split_bf16(bv[2*j], bv[2*j+1], hw[j], lw[j]);                 \
            uint32_t* dH = dyn + (st) * kStageW32 + 2 * kArrW32 +             \
                           arow * kStr32 + ahalf * 8;                         \
            uint32_t* dL = dH + kArrW32;                                      \
            *reinterpret_cast<uint4*>(dH)     = make_uint4(hw[0],hw[1],hw[2],hw[3]); \
            *reinterpret_cast<uint4*>(dH + 4) = make_uint4(hw[4],hw[5],hw[6],hw[7]); \
            *reinterpret_cast<uint4*>(dL)     = make_uint4(lw[0],lw[1],lw[2],lw[3]); \
            *reinterpret_cast<uint4*>(dL + 4) = make_uint4(lw[4],lw[5],lw[6],lw[7]); \
        }
    #define G3_COMPUTE(st)                                                    \
        _Pragma("unroll")                                                     \
        for (int s = 0; s < 2; ++s) {                                         \
            uint32_t ah[4][4], al[4][4], bh[4][2], bl[4][2];                  \
            _Pragma("unroll")                                                 \
            for (int mi = 0; mi < 4; ++mi) {                                  \
                uint32_t ad = sb + ((uint32_t)((st) * kStageW32) + aoff +     \
                                    (uint32_t)(mi * 16 * kStr32 + s * 8)) * 4;\
                LDM4(ah[mi][0], ah[mi][1], ah[mi][2], ah[mi][3], ad)          \
                LDM4(al[mi][0], al[mi][1], al[mi][2], al[mi][3],              \
                     ad + kArrW32 * 4)                                        \
            }                                                                 \
            _Pragma("unroll")                                                 \
            for (int nip = 0; nip < 2; ++nip) {                               \
                uint32_t bd = sb + ((uint32_t)((st) * kStageW32 +             \
                                    2 * kArrW32) + boff +                     \
                                    (uint32_t)(nip * 16 * kStr32 + s * 8)) * 4;\
                LDM4(bh[2*nip][0], bh[2*nip][1], bh[2*nip+1][0],              \
                     bh[2*nip+1][1], bd)                                      \
                LDM4(bl[2*nip][0], bl[2*nip][1], bl[2*nip+1][0],              \
                     bl[2*nip+1][1], bd + kArrW32 * 4)                        \
            }                                                                 \
            _Pragma("unroll")                                                 \
            for (int mi = 0; mi < 4; ++mi)                                    \
                _Pragma("unroll")                                             \
                for (int ni = 0; ni < 4; ++ni) {                              \
                    mma_bf16(acc[mi][ni], al[mi], bh[ni]);                    \
                    mma_bf16(acc[mi][ni], ah[mi], bl[ni]);                    \
                    mma_bf16(acc[mi][ni], ah[mi], bh[ni]);                    \
                }                                                             \
        }

    G3_LOAD_A(0)
    G3_LOAD_B(0)
    G3_STORE_A(0)
    G3_STORE_B(0)
    __syncthreads();

    const int nk = K >> 5;
    for (int kt = 0; kt < nk; kt += 2) {
        {
            const bool more = (kt + 1) < nk;
            if (more) {
                const int k0 = (kt + 1) << 5;
                G3_LOAD_A(k0)
                G3_LOAD_B(k0)
            }
            G3_COMPUTE(0)
            if (more) {
                G3_STORE_A(1)
                G3_STORE_B(1)
                __syncthreads();
            }
        }
        if (kt + 1 < nk) {
            const bool more = (kt + 2) < nk;
            if (more) {
                const int k0 = (kt + 2) << 5;
                G3_LOAD_A(k0)
                G3_LOAD_B(k0)
            }
            G3_COMPUTE(1)
            if (more) {
                G3_STORE_A(0)
                G3_STORE_B(0)
                __syncthreads();
            }
        }
    }

    #undef G3_LOAD_A
    #undef G3_STORE_A
    #undef G3_LOAD_B
    #undef G3_STORE_B
    #undef G3_COMPUTE

    #pragma unroll
    for (int mi = 0; mi < 4; ++mi) {
        const int r0 = m0 + wm + mi * 16 + lg;
        #pragma unroll
        for (int ni = 0; ni < 4; ++ni) {
            const int n = n0 + wn + ni * 8 + 2 * lt;
            if (r0 < effM) {
                float2 v = make_float2(acc[mi][ni][0], acc[mi][ni][1]);
                if (addsrc) {
                    float2 a = *reinterpret_cast<const float2*>(&addsrc[(size_t)r0 * ldc + n]);
                    v.x += a.x; v.y += a.y;
                }
                *reinterpret_cast<float2*>(&C[(size_t)r0 * ldc + n]) = v;
            }
            if (r0 + 8 < effM) {
                float2 v = make_float2(acc[mi][ni][2], acc[mi][ni][3]);
                if (addsrc) {
                    float2 a = *reinterpret_cast<const float2*>(&addsrc[(size_t)(r0 + 8) * ldc + n]);
                    v.x += a.x; v.y += a.y;
                }
                *reinterpret_cast<float2*>(&C[(size_t)(r0 + 8) * ldc + n]) = v;
            }
        }
    }
}

// Generic BK=32 bf16x3 GEMM kernel (attention path).
// causal==1: skip blocks above diagonal. causal==2: truncate K at m0+128.
template <bool TB>
__global__ void __launch_bounds__(256)
bgemm3_kernel(const float* __restrict__ A, const float* __restrict__ B,
              float* __restrict__ C, int M, int N, int K,
              int lda, int ldb, int ldc,
              long long sA, long long sB, long long sC,
              const int* __restrict__ mlim, int causal,
              const float* __restrict__ addsrc)
{
    const int bz = blockIdx.z;
    A += (size_t)bz * (size_t)sA;
    B += (size_t)bz * (size_t)sB;
    C += (size_t)bz * (size_t)sC;

    int effM = M;
    if (mlim) { int c = mlim[bz]; if (c < effM) effM = c; }

    const int m0 = blockIdx.y * 128;
    const int n0 = blockIdx.x * 128;
    if (m0 >= effM) return;
    if (causal == 1 && n0 > m0 + 127) return;
    if (causal == 2) { int kl = m0 + 128; if (kl < K) K = kl; }

    bg3_core<TB>(A, B, C, effM, K, lda, ldb, ldc, m0, n0, addsrc);
}

// Fused QKV projection: one grid covers wq (32 n-blocks), wk (4), wv (4).
__global__ void __launch_bounds__(256)
qkv_kernel(const float* __restrict__ A,
           const float* __restrict__ wq, const float* __restrict__ wk,
           const float* __restrict__ wv,
           float* __restrict__ qo, float* __restrict__ ko, float* __restrict__ vo)
{
    const int bx = blockIdx.x;
    const float* B; float* C; int ld, n0;
    if (bx < 32)      { B = wq; C = qo; ld = kNH  * kHD; n0 = bx * 128; }
    else if (bx < 36) { B = wk; C = ko; ld = kNKV * kHD; n0 = (bx - 32) * 128; }
    else              { B = wv; C = vo; ld = kNKV * kHD; n0 = (bx - 36) * 128; }
    bg3_core<false>(A, B, C, kT, kHID, kHID, ld, ld,
                    blockIdx.y * 128, n0, nullptr);
}

// ---------------------------------------------------------------------------
// MoE GEMM: BK=16, double-buffered static K-contiguous smem (stride 12,
// ldmatrix conflict-free), ldmatrix fragments, transpose-gather NN B loads
// with vectorized uint4 stores. Smem: 2 x 4 x 128 x 12 x 4 = 49152 B.
// Plain launch_bounds(256) — full register budget, no spills (R14-proven).
// gsrc: optional gate buffer — epilogue stores silu(g)*acc (fused SwiGLU).
// nk = K/16 even (128, 48).
// ---------------------------------------------------------------------------
static constexpr int kStr16  = 12;
static constexpr int kArrW16 = 128 * kStr16;

__global__ void __launch_bounds__(256)
moe3_kernel(const float* __restrict__ A, const float* __restrict__ B,
            float* __restrict__ C, int M, int N, int K,
            int lda, int ldb, int ldc,
            long long sA, long long sB, long long sC,
            const int* __restrict__ mlim,
            const float* __restrict__ gsrc)
{
    const int bz = blockIdx.z;
    A += (size_t)bz * (size_t)sA;
    B += (size_t)bz * (size_t)sB;
    C += (size_t)bz * (size_t)sC;

    int effM = M;
    if (mlim) { int c = mlim[bz]; if (c < effM) effM = c; }

    const int m0 = blockIdx.y * 128;
    const int n0 = blockIdx.x * 128;
    if (m0 >= effM) return;

    const float* gS = gsrc ? (gsrc + (size_t)bz * (size_t)sC) : nullptr;

    __shared__ __align__(16) uint32_t Ah[2][kArrW16];
    __shared__ __align__(16) uint32_t Al[2][kArrW16];
    __shared__ __align__(16) uint32_t Bh[2][kArrW16];
    __shared__ __align__(16) uint32_t Bl[2][kArrW16];

    const int tid  = threadIdx.x;
    const int warp = tid >> 5;
    const int lane = tid & 31;
    const int wm   = (warp & 1) * 64;
    const int wn   = (warp >> 1) * 32;
    const int lg   = lane >> 2;
    const int lt   = lane & 3;

    const int arow = tid >> 1;
    const int ahalf= tid & 1;
    const int acol = ahalf * 8;

    const uint32_t sbAh = (uint32_t)__cvta_generic_to_shared(Ah);
    const uint32_t sbAl = (uint32_t)__cvta_generic_to_shared(Al);
    const uint32_t sbBh = (uint32_t)__cvta_generic_to_shared(Bh);
    const uint32_t sbBl = (uint32_t)__cvta_generic_to_shared(Bl);

    const uint32_t aoff =
        (uint32_t)((wm + (lane & 15)) * kStr16 + ((lane >> 4) << 2));
    const uint32_t boff =
        (uint32_t)((wn + (lane & 7) + ((lane & 16) >> 1)) * kStr16 +
                   (((lane >> 3) & 1) << 2));

    float acc[4][4][4];
    #pragma unroll
    for (int i = 0; i < 4; ++i)
        #pragma unroll
        for (int j = 0; j < 4; ++j)
            #pragma unroll
            for (int l = 0; l < 4; ++l) acc[i][j][l] = 0.f;

    float av[8], bv[8];

    #define M3_LOAD_A(k0)                                                     \
        {                                                                     \
            int m = m0 + arow;                                                \
            if (m < effM) {                                                   \
                const float* p = A + (size_t)m * lda + (k0) + acol;           \
                *reinterpret_cast<float4*>(&av[0]) = *reinterpret_cast<const float4*>(p);     \
                *reinterpret_cast<float4*>(&av[4]) = *reinterpret_cast<const float4*>(p + 4); \
            } else {                                                          \
                _Pragma("unroll")                                             \
                for (int j = 0; j < 8; ++j) av[j] = 0.f;                      \
            }                                                                 \
        }
    #define M3_STORE_A(st)                                                    \
        {                                                                     \
            uint32_t hw[4], lw[4];                                            \
            _Pragma("unroll")                                                 \
            for (int j = 0; j < 4; ++j)                                       \
                split_bf16(av[2*j], av[2*j+1], hw[j], lw[j]);                 \
            uint32_t* dH = &Ah[st][arow * kStr16 + ahalf * 4];                \
            uint32_t* dL = &Al[st][arow * kStr16 + ahalf * 4];                \
            *reinterpret_cast<uint4*>(dH) = make_uint4(hw[0],hw[1],hw[2],hw[3]); \
            *reinterpret_cast<uint4*>(dL) = make_uint4(lw[0],lw[1],lw[2],lw[3]); \
        }
    #define M3_LOAD_B(k0)                                                     \
        {                                                                     \
            const float* p = B + (size_t)((k0) + ahalf * 8) * ldb + n0 + arow;\
            _Pragma("unroll")                                                 \
            for (int j = 0; j < 8; ++j) bv[j] = p[(size_t)j * ldb];           \
        }
    #define M3_STORE_B(st)                                                    \
        {                                                                     \
            uint32_t hw[4], lw[4];                                            \
            _Pragma("unroll")                                                 \
            for (int j = 0; j < 4; ++j)                                       \
                split_bf16(bv[2*j], bv[2*j+1], hw[j], lw[j]);                 \
            uint32_t* dH = &Bh[st][arow * kStr16 + ahalf * 4];                \
            uint32_t* dL = &Bl[st][arow * kStr16 + ahalf * 4];                \
            *reinterpret_cast<uint4*>(dH) = make_uint4(hw[0],hw[1],hw[2],hw[3]); \
            *reinterpret_cast<uint4*>(dL) = make_uint4(lw[0],lw[1],lw[2],lw[3]); \
        }
    #define M3_COMPUTE(st)                                                    \
        {                                                                     \
            uint32_t ah[4][4], al[4][4], bh[4][2], bl[4][2];                  \
            _Pragma("unroll")                                                 \
            for (int mi = 0; mi < 4; ++mi) {                                  \
                uint32_t woff = (uint32_t)((st) * kArrW16) + aoff +           \
                                (uint32_t)(mi * 16 * kStr16);                 \
                LDM4(ah[mi][0], ah[mi][1], ah[mi][2], ah[mi][3],              \
                     sbAh + woff * 4)                                         \
                LDM4(al[mi][0], al[mi][1], al[mi][2], al[mi][3],              \
                     sbAl + woff * 4)                                         \
            }                                                                 \
            _Pragma("unroll")                                                 \
            for (int nip = 0; nip < 2; ++nip) {                               \
                uint32_t woff = (uint32_t)((st) * kArrW16) + boff +           \
                                (uint32_t)(nip * 16 * kStr16);                \
                LDM4(bh[2*nip][0], bh[2*nip][1], bh[2*nip+1][0],              \
                     bh[2*nip+1][1], sbBh + woff * 4)                         \
                LDM4(bl[2*nip][0], bl[2*nip][1], bl[2*nip+1][0],              \
                     bl[2*nip+1][1], sbBl + woff * 4)                         \
            }                                                                 \
            _Pragma("unroll")                                                 \
            for (int mi = 0; mi < 4; ++mi)                                    \
                _Pragma("unroll")                                             \
                for (int ni = 0; ni < 4; ++ni) {                              \
                    mma_bf16(acc[mi][ni], al[mi], bh[ni]);                    \
                    mma_bf16(acc[mi][ni], ah[mi], bl[ni]);                    \
                    mma_bf16(acc[mi][ni], ah[mi], bh[ni]);                    \
                }                                                             \
        }

    M3_LOAD_A(0)
    M3_LOAD_B(0)
    M3_STORE_A(0)
    M3_STORE_B(0)
    __syncthreads();

    const int nk = K >> 4;
    for (int kt = 0; kt < nk; kt += 2) {
        {
            const bool more = (kt + 1) < nk;
            if (more) {
                const int k0 = (kt + 1) << 4;
                M3_LOAD_A(k0)
                M3_LOAD_B(k0)
            }
            M3_COMPUTE(0)
            if (more) {
                M3_STORE_A(1)
                M3_STORE_B(1)
                __syncthreads();
            }
        }
        if (kt + 1 < nk) {
            const bool more = (kt + 2) < nk;
            if (more) {
                const int k0 = (kt + 2) << 4;
                M3_LOAD_A(k0)
                M3_LOAD_B(k0)
            }
            M3_COMPUTE(1)
            if (more) {
                M3_STORE_A(0)
                M3_STORE_B(0)
                __syncthreads();
            }
        }
    }

    #undef M3_LOAD_A
    #undef M3_STORE_A
    #undef M3_LOAD_B
    #undef M3_STORE_B
    #undef M3_COMPUTE

    #pragma unroll
    for (int mi = 0; mi < 4; ++mi) {
        const int r0 = m0 + wm + mi * 16 + lg;
        #pragma unroll
        for (int ni = 0; ni < 4; ++ni) {
            const int n = n0 + wn + ni * 8 + 2 * lt;
            if (r0 < effM) {
                float2 v = make_float2(acc[mi][ni][0], acc[mi][ni][1]);
                if (gS) {
                    float2 g = *reinterpret_cast<const float2*>(&gS[(size_t)r0 * ldc + n]);
                    v.x *= g.x / (1.f + expf(-g.x));
                    v.y *= g.y / (1.f + expf(-g.y));
                }
                *reinterpret_cast<float2*>(&C[(size_t)r0 * ldc + n]) = v;
            }
            if (r0 + 8 < effM) {
                float2 v = make_float2(acc[mi][ni][2], acc[mi][ni][3]);
                if (gS) {
                    float2 g = *reinterpret_cast<const float2*>(&gS[(size_t)(r0 + 8) * ldc + n]);
                    v.x *= g.x / (1.f + expf(-g.x));
                    v.y *= g.y / (1.f + expf(-g.y));
                }
                *reinterpret_cast<float2*>(&C[(size_t)(r0 + 8) * ldc + n]) = v;
            }
        }
    }
}

// ---------------------------------------------------------------------------
// Exact fp32 SGEMM (gate logits only: feeds discrete top-k routing).
// ---------------------------------------------------------------------------
template <bool TB>
__global__ void __launch_bounds__(256)
sgemm_kernel(const float* __restrict__ A, const float* __restrict__ B,
             float* __restrict__ C, int M, int N, int K,
             int lda, int ldb, int ldc,
             long long sA, long long sB, long long sC,
             const int* __restrict__ mlim, int causal)
{
    const int bz = blockIdx.z;
    A += (size_t)bz * (size_t)sA;
    B += (size_t)bz * (size_t)sB;
    C += (size_t)bz * (size_t)sC;

    int effM = M;
    if (mlim) { int c = mlim[bz]; if (c < effM) effM = c; }

    const int m0 = blockIdx.y * 128;
    const int n0 = blockIdx.x * 128;
    if (m0 >= effM) return;
    if (causal && n0 > m0 + 127) return;

    __shared__ __align__(16) float As[8][128];
    __shared__ __align__(16) float Bs[8][128];

    const int tid  = threadIdx.x;
    const int rowL = tid >> 1;
    const int kL   = (tid & 1) * 4;
    const int kB   = tid >> 5;
    const int nb   = tid & 31;
    const int ty   = tid >> 4, tx = tid & 15;

    float acc[8][8];
    #pragma unroll
    for (int i = 0; i < 8; ++i)
        #pragma unroll
        for (int j = 0; j < 8; ++j) acc[i][j] = 0.f;

    float ra[4], rb[4];

    {
        #pragma unroll
        for (int i = 0; i < 4; ++i) {
            int m = m0 + rowL, k = kL + i;
            ra[i] = (m < effM && k < K) ? A[(size_t)m * lda + k] : 0.f;
        }
        if (TB) {
            #pragma unroll
            for (int i = 0; i < 4; ++i) {
                int n = n0 + rowL, k = kL + i;
                rb[i] = (n < N && k < K) ? B[(size_t)n * ldb + k] : 0.f;
            }
        } else {
            #pragma unroll
            for (int i = 0; i < 4; ++i) {
                int n = n0 + nb + 32 * i;
                rb[i] = (n < N && kB < K) ? B[(size_t)kB * ldb + n] : 0.f;
            }
        }
        #pragma unroll
        for (int i = 0; i < 4; ++i) As[kL + i][rowL] = ra[i];
        if (TB) {
            #pragma unroll
            for (int i = 0; i < 4; ++i) Bs[kL + i][rowL] = rb[i];
        } else {
            #pragma unroll
            for (int i = 0; i < 4; ++i) Bs[kB][nb + 32 * i] = rb[i];
        }
    }
    __syncthreads();

    const int nk = (K + 7) >> 3;
    for (int kt = 0; kt < nk; ++kt) {
        const bool more = (kt + 1) < nk;
        const int k0 = (kt + 1) << 3;
        if (more) {
            #pragma unroll
            for (int i = 0; i < 4; ++i) {
                int m = m0 + rowL, k = k0 + kL + i;
                ra[i] = (m < effM && k < K) ? A[(size_t)m * lda + k] : 0.f;
            }
            if (TB) {
                #pragma unroll
                for (int i = 0; i < 4; ++i) {
                    int n = n0 + rowL, k = k0 + kL + i;
                    rb[i] = (n < N && k < K) ? B[(size_t)n * ldb + k] : 0.f;
                }
            } else {
                #pragma unroll
                for (int i = 0; i < 4; ++i) {
                    int n = n0 + nb + 32 * i, k = k0 + kB;
                    rb[i] = (n < N && k < K) ? B[(size_t)k * ldb + n] : 0.f;
                }
            }
        }
        #pragma unroll
        for (int kk = 0; kk < 8; ++kk) {
            float a[8], b[8];
            *reinterpret_cast<float4*>(&a[0]) = *reinterpret_cast<const float4*>(&As[kk][ty * 8]);
            *reinterpret_cast<float4*>(&a[4]) = *reinterpret_cast<const float4*>(&As[kk][ty * 8 + 4]);
            *reinterpret_cast<float4*>(&b[0]) = *reinterpret_cast<const float4*>(&Bs[kk][tx * 8]);
            *reinterpret_cast<float4*>(&b[4]) = *reinterpret_cast<const float4*>(&Bs[kk][tx * 8 + 4]);
            #pragma unroll
            for (int i = 0; i < 8; ++i)
                #pragma unroll
                for (int j = 0; j < 8; ++j)
                    acc[i][j] = fmaf(a[i], b[j], acc[i][j]);
        }
        __syncthreads();
        if (more) {
            #pragma unroll
            for (int i = 0; i < 4; ++i) As[kL + i][rowL] = ra[i];
            if (TB) {
                #pragma unroll
                for (int i = 0; i < 4; ++i) Bs[kL + i][rowL] = rb[i];
            } else {
                #pragma unroll
                for (int i = 0; i < 4; ++i) Bs[kB][nb + 32 * i] = rb[i];
            }
            __syncthreads();
        }
    }

    #pragma unroll
    for (int i = 0; i < 8; ++i) {
        int m = m0 + ty * 8 + i;
        if (m >= effM) continue;
        #pragma unroll
        for (int j = 0; j < 8; ++j) {
            int n = n0 + tx * 8 + j;
            if (n < N) C[(size_t)m * ldc + n] = acc[i][j];
        }
    }
}

// ---------------------------------------------------------------------------
// RMSNorm over rows of [*, HID]
// ---------------------------------------------------------------------------
__global__ void rmsnorm_kernel(const float* __restrict__ x,
                               const float* __restrict__ w,
                               float* __restrict__ y)
{
    const int t = blockIdx.x, tid = threadIdx.x;
    const float* xr = x + (size_t)t * kHID;
    float s = 0.f;
    for (int i = tid; i < kHID; i += 256) { float v = xr[i]; s += v * v; }
    __shared__ float red[256];
    red[tid] = s; __syncthreads();
    for (int st = 128; st > 0; st >>= 1) {
        if (tid < st) red[tid] += red[tid + st];
        __syncthreads();
    }
    const float sc = rsqrtf(red[0] / (float)kHID + kEPS);
    for (int i = tid; i < kHID; i += 256)
        y[(size_t)t * kHID + i] = xr[i] * sc * w[i];
}

// ---------------------------------------------------------------------------
// Fused q/k rmsnorm + rope + GQA replication + v replication.
// ---------------------------------------------------------------------------
__global__ void rope_kernel(const float* __restrict__ qbuf,
                            const float* __restrict__ kbuf,
                            const float* __restrict__ vbuf,
                            const int* __restrict__ pos,
                            const float* __restrict__ qw,
                            const float* __restrict__ kw,
                            float* __restrict__ qh,
                            float* __restrict__ krep,
                            float* __restrict__ vrep)
{
    const int t = blockIdx.x, y = blockIdx.y, d = threadIdx.x;
    constexpr int kRep = kNH / kNKV;
    constexpr float kNegLog2Theta = -19.931568569324174f / 64.0f;

    if (y >= 36) {
        const int kv = y - 36;
        float v = vbuf[(size_t)t * (kNKV * kHD) + kv * kHD + d];
        #pragma unroll
        for (int r = 0; r < kRep; ++r)
            vrep[((size_t)(kv * kRep + r) * kT + t) * kHD + d] = v;
        return;
    }

    const bool isq = (y < 32);
    const float* src = isq ? (qbuf + (size_t)t * (kNH * kHD) + y * kHD)
                           : (kbuf + (size_t)t * (kNKV * kHD) + (y - 32) * kHD);
    const float* w = isq ? qw : kw;

    float v = src[d];
    __shared__ float red[kHD];
    red[d] = v * v;
    __syncthreads();
    #pragma unroll
    for (int s = 64; s > 0; s >>= 1) {
        if (d < s) red[d] += red[d + s];
        __syncthreads();
    }
    const float sc = rsqrtf(red[0] / (float)kHD + kEPS);
    __syncthreads();
    red[d] = v * sc * w[d];
    __syncthreads();

    const int j = (d < 64) ? d : d - 64;
    const float f = (float)pos[t] * exp2f((float)j * kNegLog2Theta);
    float cs, sn;
    sincosf(f, &sn, &cs);
    const float o = (d < 64) ? (red[d] * cs - red[d + 64] * sn)
                             : (red[d - 64] * sn + red[d] * cs);

    if (isq) {
        qh[((size_t)y * kT + t) * kHD + d] = o;
    } else {
        const int kv = y - 32;
        #pragma unroll
        for (int r = 0; r < kRep; ++r)
            krep[((size_t)(kv * kRep + r) * kT + t) * kHD + d] = o;
    }
}

// ---------------------------------------------------------------------------
// Causal row softmax. Zero-fills only to the 128-aligned block end.
// ---------------------------------------------------------------------------
__global__ void softmax_kernel(float* __restrict__ sc)
{
    const int h = blockIdx.x, q = blockIdx.y, tid = threadIdx.x;
    float* row = sc + ((size_t)h * kT + q) * kT;
    const int len = q + 1;
    const int fill = ((q >> 7) + 1) << 7;
    const float scale = 0.08838834764831845f;

    __shared__ float red[256];
    float m = -1e30f;
    for (int i = tid; i < len; i += 256) m = fmaxf(m, row[i]);
    red[tid] = m; __syncthreads();
    for (int st = 128; st > 0; st >>= 1) {
        if (tid < st) red[tid] = fmaxf(red[tid], red[tid + st]);
        __syncthreads();
    }
    m = red[0] * scale;
    __syncthreads();

    float s = 0.f;
    for (int i = tid; i < len; i += 256) s += expf(row[i] * scale - m);
    red[tid] = s; __syncthreads();
    for (int st = 128; st > 0; st >>= 1) {
        if (tid < st) red[tid] += red[tid + st];
        __syncthreads();
    }
    const float inv = 1.f / red[0];

    for (int i = tid; i < fill; i += 256) {
        float v = (i < len) ? expf(row[i] * scale - m) * inv : 0.f;
        row[i] = v;
    }
}

// ---------------------------------------------------------------------------
// Gate softmax + top-8
// ---------------------------------------------------------------------------
__global__ void topk_kernel(const float* __restrict__ logits,
                            float* __restrict__ topw, int* __restrict__ topi)
{
    const int t = blockIdx.x, lane = threadIdx.x;
    float l0 = logits[t * kE + lane];
    float l1 = logits[t * kE + 32 + lane];
    float m = fmaxf(l0, l1);
    for (int off = 16; off; off >>= 1) m = fmaxf(m, __shfl_xor_sync(0xffffffffu, m, off));
    float e0 = expf(l0 - m), e1 = expf(l1 - m);
    float s = e0 + e1;
    for (int off = 16; off; off >>= 1) s += __shfl_xor_sync(0xffffffffu, s, off);
    float p0 = e0 / s, p1 = e1 / s;

    float sel[kK]; int seli[kK];
    #pragma unroll
    for (int k = 0; k < kK; ++k) {
        float v = p0; int idx = lane;
        if (p1 > v) { v = p1; idx = lane + 32; }
        for (int off = 16; off; off >>= 1) {
            float ov = __shfl_xor_sync(0xffffffffu, v, off);
            int   oi = __shfl_xor_sync(0xffffffffu, idx, off);
            if (ov > v || (ov == v && oi < idx)) { v = ov; idx = oi; }
        }
        sel[k] = v; seli[k] = idx;
        if (idx == lane)      p0 = -1.f;
        if (idx == lane + 32) p1 = -1.f;
    }
    if (lane == 0) {
        float sum = 0.f;
        #pragma unroll
        for (int k = 0; k < kK; ++k) sum += sel[k];
        #pragma unroll
        for (int k = 0; k < kK; ++k) {
            topw[t * kK + k] = sel[k] / sum;
            topi[t * kK + k] = seli[k];
        }
    }
}

// ---------------------------------------------------------------------------
// Routing: stable (t,k)-order ranks per expert, capacity drop.
// ---------------------------------------------------------------------------
__global__ void route_kernel(const int* __restrict__ topi,
                             int* __restrict__ tok, int* __restrict__ slot,
                             int* __restrict__ cnt)
{
    const int e = blockIdx.x, tid = threadIdx.x;
    constexpr int A = kT * kK;
    constexpr int PER = A / 256;
    int c = 0;
    for (int i = 0; i < PER; ++i) c += (topi[tid * PER + i] == e);

    __shared__ int s[256];
    s[tid] = c; __syncthreads();
    for (int off = 1; off < 256; off <<= 1) {
        int v = (tid >= off) ? s[tid - off] : 0;
        __syncthreads();
        s[tid] += v;
        __syncthreads();
    }
    const int total = s[255];
    int r = s[tid] - c;

    for (int i = 0; i < PER; ++i) {
        int a = tid * PER + i;
        if (topi[a] == e) {
            if (r < kCAP) {
                tok[e * kCAP + r] = a / kK;
                slot[a] = e * kCAP + r;
            } else {
                slot[a] = -1;
            }
            ++r;
        }
    }
    if (tid == 0) cnt[e] = (total < kCAP) ? total : kCAP;
}

__global__ void gather_kernel(const float* __restrict__ h2,
                              const int* __restrict__ tok,
                              const int* __restrict__ cnt,
                              float* __restrict__ xb)
{
    const int b = blockIdx.x;
    const int e = b >> 8, r = b & (kCAP - 1);
    if (r >= cnt[e]) return;
    const int t = tok[b];
    const float4* src = reinterpret_cast<const float4*>(h2 + (size_t)t * kHID);
    float4* dst = reinterpret_cast<float4*>(xb + (size_t)b * kHID);
    for (int i = threadIdx.x; i < kHID / 4; i += blockDim.x) dst[i] = src[i];
}

__global__ void combine_kernel(const float* __restrict__ yb,
                               const int* __restrict__ slot,
                               const float* __restrict__ topw,
                               float* __restrict__ out)
{
    const int t = blockIdx.x;
    __shared__ int ss[kK];
    __shared__ float sw[kK];
    if (threadIdx.x < kK) {
        ss[threadIdx.x] = slot[t * kK + threadIdx.x];
        sw[threadIdx.x] = topw[t * kK + threadIdx.x];
    }
    __syncthreads();
    for (int c = threadIdx.x; c < kHID; c += blockDim.x) {
        float acc = 0.f;
        #pragma unroll
        for (int k = 0; k < kK; ++k) {
            int sl = ss[k];
            if (sl >= 0) acc += sw[k] * yb[(size_t)sl * kHID + c];
        }
        out[(size_t)t * kHID + c] = acc;
    }
}

// ---------------------------------------------------------------------------
// Launcher
// ---------------------------------------------------------------------------
extern "C" void kernel_launch(void* const* d_in, const int* in_sizes, int n_in,
                              void* d_out, int out_size)
{
    const float* hidden    = (const float*)d_in[0];
    const int*   pos       = (const int*)  d_in[1];
    const float* ln_in_w   = (const float*)d_in[2];
    const float* ln_post_w = (const float*)d_in[3];
    const float* q_norm_w  = (const float*)d_in[4];
    const float* k_norm_w  = (const float*)d_in[5];
    const float* wq        = (const float*)d_in[6];
    const float* wk        = (const float*)d_in[7];
    const float* wv        = (const float*)d_in[8];
    const float* wo        = (const float*)d_in[9];
    const float* gate_w    = (const float*)d_in[10];
    const float* we_gate   = (const float*)d_in[11];
    const float* we_up     = (const float*)d_in[12];
    const float* we_down   = (const float*)d_in[13];

    float* out   = (float*)d_out;
    float* resid = out + (size_t)kT * kHID;

    float *hnorm, *h2, *qbuf, *kbuf, *vbuf, *qh, *krep, *vrep, *attno,
          *scores, *logits, *topw, *xb, *gbuf, *ubuf;
    int *topi, *cnt, *tok, *slot;
    cudaGetSymbolAddress((void**)&hnorm,  g_hnorm);
    cudaGetSymbolAddress((void**)&h2,     g_h2);
    cudaGetSymbolAddress((void**)&qbuf,   g_qbuf);
    cudaGetSymbolAddress((void**)&kbuf,   g_kbuf);
    cudaGetSymbolAddress((void**)&vbuf,   g_vbuf);
    cudaGetSymbolAddress((void**)&qh,     g_qh);
    cudaGetSymbolAddress((void**)&krep,   g_krep);
    cudaGetSymbolAddress((void**)&vrep,   g_vrep);
    cudaGetSymbolAddress((void**)&attno,  g_attno);
    cudaGetSymbolAddress((void**)&scores, g_scores);
    cudaGetSymbolAddress((void**)&logits, g_logits);
    cudaGetSymbolAddress((void**)&topw,   g_topw);
    cudaGetSymbolAddress((void**)&topi,   g_topi);
    cudaGetSymbolAddress((void**)&cnt,    g_cnt);
    cudaGetSymbolAddress((void**)&tok,    g_tok);
    cudaGetSymbolAddress((void**)&slot,   g_slot);
    cudaGetSymbolAddress((void**)&xb,     g_xb);
    cudaGetSymbolAddress((void**)&gbuf,   g_gbuf);
    cudaGetSymbolAddress((void**)&ubuf,   g_ubuf);

    // Opt-in to 80KB dynamic smem for BK=32 kernels (host-side only).
    static bool attr_done = false;
    if (!attr_done) {
        cudaFuncSetAttribute(qkv_kernel,
                             cudaFuncAttributeMaxDynamicSharedMemorySize, kB32Smem);
        cudaFuncSetAttribute(bgemm3_kernel<false>,
                             cudaFuncAttributeMaxDynamicSharedMemorySize, kB32Smem);
        cudaFuncSetAttribute(bgemm3_kernel<true>,
                             cudaFuncAttributeMaxDynamicSharedMemorySize, kB32Smem);
        attr_done = true;
    }

    // 1) input RMSNorm
    rmsnorm_kernel<<<kT, 256>>>(hidden, ln_in_w, hnorm);

    // 2) fused Q/K/V projections (ldmatrix BK=32, gather NN stores)
    qkv_kernel<<<dim3(40, kT / 128, 1), 256, kB32Smem>>>(
        hnorm, wq, wk, wv, qbuf, kbuf, vbuf);

    // 3) fused q/k rmsnorm + rope (+ GQA replication) + v replication
    rope_kernel<<<dim3(kT, 40), kHD>>>(
        qbuf, kbuf, vbuf, pos, q_norm_w, k_norm_w, qh, krep, vrep);

    // 4) S = Q @ K^T (causal block skip)
    bgemm3_kernel<true><<<dim3(kT / 128, kT / 128, kNH), 256, kB32Smem>>>(
        qh, krep, scores, kT, kT, kHD, kHD, kHD, kT,
        (long long)kT * kHD, (long long)kT * kHD, (long long)kT * kT,
        nullptr, 1, nullptr);

    // 5) causal softmax (block-limited fill)
    softmax_kernel<<<dim3(kNH, kT), 256>>>(scores);

    // 6) O = P @ V (causal K-truncation)
    bgemm3_kernel<false><<<dim3(1, kT / 128, kNH), 256, kB32Smem>>>(
        scores, vrep, attno, kT, kHD, kT, kT, kHD, kNH * kHD,
        (long long)kT * kT, (long long)kT * kHD, (long long)kHD,
        nullptr, 2, nullptr);

    // 7) output projection with fused residual add -> resid
    bgemm3_kernel<false><<<dim3(kHID / 128, kT / 128, 1), 256, kB32Smem>>>(
        attno, wo, resid, kT, kHID, kNH * kHD, kNH * kHD, kHID, kHID,
        0, 0, 0, nullptr, 0, hidden);

    // 8) post-attention RMSNorm
    rmsnorm_kernel<<<kT, 256>>>(resid, ln_post_w, h2);

    // 9) gate logits (exact fp32) + top-k + routing
    sgemm_kernel<false><<<dim3(1, kT / 128, 1), 256>>>(
        h2, gate_w, logits, kT, kE, kHID, kHID, kE, kE, 0, 0, 0, nullptr, 0);
    topk_kernel <<<kT, 32>>>(logits, topw, topi);
    route_kernel<<<kE, 256>>>(topi, tok, slot, cnt);
    gather_kernel<<<kE * kCAP, 256>>>(h2, tok, cnt, xb);

    // 10) expert FFN (ldmatrix BK=16, full regs, fused SwiGLU epilogue)
    //     gate -> gbuf; up (x silu(gate)) -> ubuf; down(ubuf) -> xb
    moe3_kernel<<<dim3(kI / 128, kCAP / 128, kE), 256>>>(
        xb, we_gate, gbuf, kCAP, kI, kHID, kHID, kI, kI,
        (long long)kCAP * kHID, (long long)kHID * kI, (long long)kCAP * kI,
        cnt, nullptr);
    moe3_kernel<<<dim3(kI / 128, kCAP / 128, kE), 256>>>(
        xb, we_up, ubuf, kCAP, kI, kHID, kHID, kI, kI,
        (long long)kCAP * kHID, (long long)kHID * kI, (long long)kCAP * kI,
        cnt, gbuf);
    moe3_kernel<<<dim3(kHID / 128, kCAP / 128, kE), 256>>>(
        ubuf, we_down, xb, kCAP, kHID, kI, kI, kHID, kHID,
        (long long)kCAP * kI, (long long)kI * kHID, (long long)kCAP * kHID,
        cnt, nullptr);

    // 11) weighted combine -> out
    combine_kernel<<<kT, 256>>>(xb, slot, topw, out);
}

// round 17
// speedup vs baseline: 1.2633x; 1.2633x over previous
#include <cuda_runtime.h>
#include <cuda_bf16.h>
#include <cstdint>
#include <cmath>

// ---------------------------------------------------------------------------
// Problem dims
// ---------------------------------------------------------------------------
static constexpr int kT   = 1024;
static constexpr int kHID = 2048;
static constexpr int kNH  = 32;
static constexpr int kNKV = 4;
static constexpr int kHD  = 128;
static constexpr int kE   = 64;
static constexpr int kK   = 8;
static constexpr int kI   = 768;
static constexpr int kCAP = 256;
static constexpr float kEPS = 1e-6f;

// ---------------------------------------------------------------------------
// Static device scratch (no allocations allowed)
// ---------------------------------------------------------------------------
__device__ float g_hnorm [kT * kHID];
__device__ float g_h2    [kT * kHID];
__device__ float g_qbuf  [kT * kNH  * kHD];
__device__ float g_kbuf  [kT * kNKV * kHD];
__device__ float g_vbuf  [kT * kNKV * kHD];
__device__ float g_qh    [(size_t)kNH * kT * kHD];
__device__ float g_krep  [(size_t)kNH * kT * kHD];
__device__ float g_vrep  [(size_t)kNH * kT * kHD];
__device__ float g_attno [kT * kNH * kHD];
__device__ float g_scores[(size_t)kNH * kT * kT];
__device__ float g_logits[kT * kE];
__device__ float g_topw  [kT * kK];
__device__ int   g_topi  [kT * kK];
__device__ int   g_cnt   [kE];
__device__ int   g_tok   [kE * kCAP];
__device__ int   g_slot  [kT * kK];
__device__ float g_xb    [(size_t)kE * kCAP * kHID];
__device__ float g_gbuf  [(size_t)kE * kCAP * kI];
__device__ float g_ubuf  [(size_t)kE * kCAP * kI];

// ---------------------------------------------------------------------------
// Precision / mma helpers
// ---------------------------------------------------------------------------
__device__ __forceinline__ void split_bf16(float x0, float x1,
                                           uint32_t& hi, uint32_t& lo)
{
    __nv_bfloat16 h0 = __float2bfloat16_rn(x0);
    __nv_bfloat16 h1 = __float2bfloat16_rn(x1);
    float r0 = x0 - __bfloat162float(h0);
    float r1 = x1 - __bfloat162float(h1);
    __nv_bfloat16 l0 = __float2bfloat16_rn(r0);
    __nv_bfloat16 l1 = __float2bfloat16_rn(r1);
    hi = (uint32_t)__bfloat16_as_ushort(h0) | ((uint32_t)__bfloat16_as_ushort(h1) << 16);
    lo = (uint32_t)__bfloat16_as_ushort(l0) | ((uint32_t)__bfloat16_as_ushort(l1) << 16);
}

__device__ __forceinline__ void mma_bf16(float c[4], const uint32_t a[4],
                                         const uint32_t b[2])
{
    asm volatile(
        "mma.sync.aligned.m16n8k16.row.col.f32.bf16.bf16.f32 "
        "{%0,%1,%2,%3}, {%4,%5,%6,%7}, {%8,%9}, {%0,%1,%2,%3};\n"
        : "+f"(c[0]), "+f"(c[1]), "+f"(c[2]), "+f"(c[3])
        : "r"(a[0]), "r"(a[1]), "r"(a[2]), "r"(a[3]), "r"(b[0]), "r"(b[1]));
}

#define LDM4(R0, R1, R2, R3, ADDR)                                            \
    asm volatile(                                                             \
        "ldmatrix.sync.aligned.m8n8.x4.shared.b16 {%0,%1,%2,%3}, [%4];"       \
        : "=r"(R0), "=r"(R1), "=r"(R2), "=r"(R3) : "r"(ADDR));

// ---------------------------------------------------------------------------
// ATTENTION GEMM core: BK=32, double-buffered, K-contiguous smem
// (stride 20 words), ldmatrix fragments. NN B fills the SAME layout via a
// transpose-gather (scalar strided LDG, coalesced across threads) and uses
// the SAME vectorized uint4 stores as TB -> no store bank conflicts.
// Smem: 2 stages x 4 arrays x 128 x 20 words = 81920 B dynamic.
// ---------------------------------------------------------------------------
static constexpr int kStr32   = 20;
static constexpr int kArrW32  = 128 * kStr32;
static constexpr int kStageW32= 4 * kArrW32;
static constexpr int kB32Smem = 2 * kStageW32 * 4;

template <bool TB>
__device__ __forceinline__ void bg3_core(
    const float* __restrict__ A, const float* __restrict__ B,
    float* __restrict__ C, int effM, int K,
    int lda, int ldb, int ldc, int m0, int n0,
    const float* __restrict__ addsrc)
{
    extern __shared__ __align__(16) uint32_t dyn[];

    const int tid  = threadIdx.x;
    const int warp = tid >> 5;
    const int lane = tid & 31;
    const int wm   = (warp & 1) * 64;
    const int wn   = (warp >> 1) * 32;
    const int lg   = lane >> 2;
    const int lt   = lane & 3;

    const int arow = tid >> 1;
    const int ahalf= tid & 1;
    const int acol = ahalf * 16;

    const uint32_t sb = (uint32_t)__cvta_generic_to_shared(dyn);
    const uint32_t aoff =
        (uint32_t)((wm + (lane & 15)) * kStr32 + ((lane >> 4) << 2));
    const uint32_t boff =
        (uint32_t)((wn + (lane & 7) + ((lane & 16) >> 1)) * kStr32 +
                   (((lane >> 3) & 1) << 2));

    float acc[4][4][4];
    #pragma unroll
    for (int i = 0; i < 4; ++i)
        #pragma unroll
        for (int j = 0; j < 4; ++j)
            #pragma unroll
            for (int l = 0; l < 4; ++l) acc[i][j][l] = 0.f;

    float av[16], bv[16];

    #define G3_LOAD_A(k0)                                                     \
        {                                                                     \
            int m = m0 + arow;                                                \
            if (m < effM) {                                                   \
                const float* p = A + (size_t)m * lda + (k0) + acol;           \
                *reinterpret_cast<float4*>(&av[0])  = *reinterpret_cast<const float4*>(p);     \
                *reinterpret_cast<float4*>(&av[4])  = *reinterpret_cast<const float4*>(p + 4); \
                *reinterpret_cast<float4*>(&av[8])  = *reinterpret_cast<const float4*>(p + 8); \
                *reinterpret_cast<float4*>(&av[12]) = *reinterpret_cast<const float4*>(p + 12);\
            } else {                                                          \
                _Pragma("unroll")                                             \
                for (int j = 0; j < 16; ++j) av[j] = 0.f;                     \
            }                                                                 \
        }
    #define G3_STORE_A(st)                                                    \
        {                                                                     \
            uint32_t hw[8], lw[8];                                            \
            _Pragma("unroll")                                                 \
            for (int j = 0; j < 8; ++j)                                       \
                split_bf16(av[2*j], av[2*j+1], hw[j], lw[j]);                 \
            uint32_t* dH = dyn + (st) * kStageW32 + arow * kStr32 + ahalf * 8;\
            uint32_t* dL = dH + kArrW32;                                      \
            *reinterpret_cast<uint4*>(dH)     = make_uint4(hw[0],hw[1],hw[2],hw[3]); \
            *reinterpret_cast<uint4*>(dH + 4) = make_uint4(hw[4],hw[5],hw[6],hw[7]); \
            *reinterpret_cast<uint4*>(dL)     = make_uint4(lw[0],lw[1],lw[2],lw[3]); \
            *reinterpret_cast<uint4*>(dL + 4) = make_uint4(lw[4],lw[5],lw[6],lw[7]); \
        }
    #define G3_LOAD_B(k0)                                                     \
        if (TB) {                                                             \
            const float* p = B + (size_t)(n0 + arow) * ldb + (k0) + acol;     \
            *reinterpret_cast<float4*>(&bv[0])  = *reinterpret_cast<const float4*>(p);     \
            *reinterpret_cast<float4*>(&bv[4])  = *reinterpret_cast<const float4*>(p + 4); \
            *reinterpret_cast<float4*>(&bv[8])  = *reinterpret_cast<const float4*>(p + 8); \
            *reinterpret_cast<float4*>(&bv[12]) = *reinterpret_cast<const float4*>(p + 12);\
        } else {                                                              \
            const float* p = B + (size_t)((k0) + ahalf * 16) * ldb + n0 + arow; \
            _Pragma("unroll")                                                 \
            for (int j = 0; j < 16; ++j) bv[j] = p[(size_t)j * ldb];          \
        }
    #define G3_STORE_B(st)                                                    \
        {                                                                     \
            uint32_t hw[8], lw[8];                                            \
            _Pragma("unroll")                                                 \
            for (int j = 0; j < 8; ++j)                                       \
                split_bf16(bv[2*j], bv[2*j+1], hw[j], lw[j]);                 \
            uint32_t* dH = dyn + (st) * kStageW32 + 2 * kArrW32 +             \
                           arow * kStr32 + ahalf * 8;                         \
            uint32_t* dL = dH + kArrW32;                                      \
            *reinterpret_cast<uint4*>(dH)     = make_uint4(hw[0],hw[1],hw[2],hw[3]); \
            *reinterpret_cast<uint4*>(dH + 4) = make_uint4(hw[4],hw[5],hw[6],hw[7]); \
            *reinterpret_cast<uint4*>(dL)     = make_uint4(lw[0],lw[1],lw[2],lw[3]); \
            *reinterpret_cast<uint4*>(dL + 4) = make_uint4(lw[4],lw[5],lw[6],lw[7]); \
        }
    #define G3_COMPUTE(st)                                                    \
        _Pragma("unroll")                                                     \
        for (int s = 0; s < 2; ++s) {                                         \
            uint32_t ah[4][4], al[4][4], bh[4][2], bl[4][2];                  \
            _Pragma("unroll")                                                 \
            for (int mi = 0; mi < 4; ++mi) {                                  \
                uint32_t ad = sb + ((uint32_t)((st) * kStageW32) + aoff +     \
                                    (uint32_t)(mi * 16 * kStr32 + s * 8)) * 4;\
                LDM4(ah[mi][0], ah[mi][1], ah[mi][2], ah[mi][3], ad)          \
                LDM4(al[mi][0], al[mi][1], al[mi][2], al[mi][3],              \
                     ad + kArrW32 * 4)                                        \
            }                                                                 \
            _Pragma("unroll")                                                 \
            for (int nip = 0; nip < 2; ++nip) {                               \
                uint32_t bd = sb + ((uint32_t)((st) * kStageW32 +             \
                                    2 * kArrW32) + boff +                     \
                                    (uint32_t)(nip * 16 * kStr32 + s * 8)) * 4;\
                LDM4(bh[2*nip][0], bh[2*nip][1], bh[2*nip+1][0],              \
                     bh[2*nip+1][1], bd)                                      \
                LDM4(bl[2*nip][0], bl[2*nip][1], bl[2*nip+1][0],              \
                     bl[2*nip+1][1], bd + kArrW32 * 4)                        \
            }                                                                 \
            _Pragma("unroll")                                                 \
            for (int mi = 0; mi < 4; ++mi)                                    \
                _Pragma("unroll")                                             \
                for (int ni = 0; ni < 4; ++ni) {                              \
                    mma_bf16(acc[mi][ni], al[mi], bh[ni]);                    \
                    mma_bf16(acc[mi][ni], ah[mi], bl[ni]);                    \
                    mma_bf16(acc[mi][ni], ah[mi], bh[ni]);                    \
                }                                                             \
        }

    G3_LOAD_A(0)
    G3_LOAD_B(0)
    G3_STORE_A(0)
    G3_STORE_B(0)
    __syncthreads();

    const int nk = K >> 5;
    for (int kt = 0; kt < nk; kt += 2) {
        {
            const bool more = (kt + 1) < nk;
            if (more) {
                const int k0 = (kt + 1) << 5;
                G3_LOAD_A(k0)
                G3_LOAD_B(k0)
            }
            G3_COMPUTE(0)
            if (more) {
                G3_STORE_A(1)
                G3_STORE_B(1)
                __syncthreads();
            }
        }
        if (kt + 1 < nk) {
            const bool more = (kt + 2) < nk;
            if (more) {
                const int k0 = (kt + 2) << 5;
                G3_LOAD_A(k0)
                G3_LOAD_B(k0)
            }
            G3_COMPUTE(1)
            if (more) {
                G3_STORE_A(0)
                G3_STORE_B(0)
                __syncthreads();
            }
        }
    }

    #undef G3_LOAD_A
    #undef G3_STORE_A
    #undef G3_LOAD_B
    #undef G3_STORE_B
    #undef G3_COMPUTE

    #pragma unroll
    for (int mi = 0; mi < 4; ++mi) {
        const int r0 = m0 + wm + mi * 16 + lg;
        #pragma unroll
        for (int ni = 0; ni < 4; ++ni) {
            const int n = n0 + wn + ni * 8 + 2 * lt;
            if (r0 < effM) {
                float2 v = make_float2(acc[mi][ni][0], acc[mi][ni][1]);
                if (addsrc) {
                    float2 a = *reinterpret_cast<const float2*>(&addsrc[(size_t)r0 * ldc + n]);
                    v.x += a.x; v.y += a.y;
                }
                *reinterpret_cast<float2*>(&C[(size_t)r0 * ldc + n]) = v;
            }
            if (r0 + 8 < effM) {
                float2 v = make_float2(acc[mi][ni][2], acc[mi][ni][3]);
                if (addsrc) {
                    float2 a = *reinterpret_cast<const float2*>(&addsrc[(size_t)(r0 + 8) * ldc + n]);
                    v.x += a.x; v.y += a.y;
                }
                *reinterpret_cast<float2*>(&C[(size_t)(r0 + 8) * ldc + n]) = v;
            }
        }
    }
}

// Generic BK=32 bf16x3 GEMM kernel (attention path).
// causal==1: skip blocks above diagonal. causal==2: truncate K at m0+128.
template <bool TB>
__global__ void __launch_bounds__(256)
bgemm3_kernel(const float* __restrict__ A, const float* __restrict__ B,
              float* __restrict__ C, int M, int N, int K,
              int lda, int ldb, int ldc,
              long long sA, long long sB, long long sC,
              const int* __restrict__ mlim, int causal,
              const float* __restrict__ addsrc)
{
    const int bz = blockIdx.z;
    A += (size_t)bz * (size_t)sA;
    B += (size_t)bz * (size_t)sB;
    C += (size_t)bz * (size_t)sC;

    int effM = M;
    if (mlim) { int c = mlim[bz]; if (c < effM) effM = c; }

    const int m0 = blockIdx.y * 128;
    const int n0 = blockIdx.x * 128;
    if (m0 >= effM) return;
    if (causal == 1 && n0 > m0 + 127) return;
    if (causal == 2) { int kl = m0 + 128; if (kl < K) K = kl; }

    bg3_core<TB>(A, B, C, effM, K, lda, ldb, ldc, m0, n0, addsrc);
}

// Fused QKV projection: one grid covers wq (32 n-blocks), wk (4), wv (4).
__global__ void __launch_bounds__(256)
qkv_kernel(const float* __restrict__ A,
           const float* __restrict__ wq, const float* __restrict__ wk,
           const float* __restrict__ wv,
           float* __restrict__ qo, float* __restrict__ ko, float* __restrict__ vo)
{
    const int bx = blockIdx.x;
    const float* B; float* C; int ld, n0;
    if (bx < 32)      { B = wq; C = qo; ld = kNH  * kHD; n0 = bx * 128; }
    else if (bx < 36) { B = wk; C = ko; ld = kNKV * kHD; n0 = (bx - 32) * 128; }
    else              { B = wv; C = vo; ld = kNKV * kHD; n0 = (bx - 36) * 128; }
    bg3_core<false>(A, B, C, kT, kHID, kHID, ld, ld,
                    blockIdx.y * 128, n0, nullptr);
}

// ---------------------------------------------------------------------------
// MoE GEMM: BK=16, double-buffered static K-contiguous smem (stride 12,
// ldmatrix conflict-free), ldmatrix fragments, transpose-gather NN B loads
// with vectorized uint4 stores. Smem: 2 x 4 x 128 x 12 x 4 = 49152 B.
// Plain epilogue (R14-proven; no SwiGLU fusion — measured regression).
// nk = K/16 even (128, 48).
// ---------------------------------------------------------------------------
static constexpr int kStr16  = 12;
static constexpr int kArrW16 = 128 * kStr16;

__global__ void __launch_bounds__(256)
moe3_kernel(const float* __restrict__ A, const float* __restrict__ B,
            float* __restrict__ C, int M, int N, int K,
            int lda, int ldb, int ldc,
            long long sA, long long sB, long long sC,
            const int* __restrict__ mlim)
{
    const int bz = blockIdx.z;
    A += (size_t)bz * (size_t)sA;
    B += (size_t)bz * (size_t)sB;
    C += (size_t)bz * (size_t)sC;

    int effM = M;
    if (mlim) { int c = mlim[bz]; if (c < effM) effM = c; }

    const int m0 = blockIdx.y * 128;
    const int n0 = blockIdx.x * 128;
    if (m0 >= effM) return;

    __shared__ __align__(16) uint32_t Ah[2][kArrW16];
    __shared__ __align__(16) uint32_t Al[2][kArrW16];
    __shared__ __align__(16) uint32_t Bh[2][kArrW16];
    __shared__ __align__(16) uint32_t Bl[2][kArrW16];

    const int tid  = threadIdx.x;
    const int warp = tid >> 5;
    const int lane = tid & 31;
    const int wm   = (warp & 1) * 64;
    const int wn   = (warp >> 1) * 32;
    const int lg   = lane >> 2;
    const int lt   = lane & 3;

    const int arow = tid >> 1;
    const int ahalf= tid & 1;
    const int acol = ahalf * 8;

    const uint32_t sbAh = (uint32_t)__cvta_generic_to_shared(Ah);
    const uint32_t sbAl = (uint32_t)__cvta_generic_to_shared(Al);
    const uint32_t sbBh = (uint32_t)__cvta_generic_to_shared(Bh);
    const uint32_t sbBl = (uint32_t)__cvta_generic_to_shared(Bl);

    const uint32_t aoff =
        (uint32_t)((wm + (lane & 15)) * kStr16 + ((lane >> 4) << 2));
    const uint32_t boff =
        (uint32_t)((wn + (lane & 7) + ((lane & 16) >> 1)) * kStr16 +
                   (((lane >> 3) & 1) << 2));

    float acc[4][4][4];
    #pragma unroll
    for (int i = 0; i < 4; ++i)
        #pragma unroll
        for (int j = 0; j < 4; ++j)
            #pragma unroll
            for (int l = 0; l < 4; ++l) acc[i][j][l] = 0.f;

    float av[8], bv[8];

    #define M3_LOAD_A(k0)                                                     \
        {                                                                     \
            int m = m0 + arow;                                                \
            if (m < effM) {                                                   \
                const float* p = A + (size_t)m * lda + (k0) + acol;           \
                *reinterpret_cast<float4*>(&av[0]) = *reinterpret_cast<const float4*>(p);     \
                *reinterpret_cast<float4*>(&av[4]) = *reinterpret_cast<const float4*>(p + 4); \
            } else {                                                          \
                _Pragma("unroll")                                             \
                for (int j = 0; j < 8; ++j) av[j] = 0.f;                      \
            }                                                                 \
        }
    #define M3_STORE_A(st)                                                    \
        {                                                                     \
            uint32_t hw[4], lw[4];                                            \
            _Pragma("unroll")                                                 \
            for (int j = 0; j < 4; ++j)                                       \
                split_bf16(av[2*j], av[2*j+1], hw[j], lw[j]);                 \
            uint32_t* dH = &Ah[st][arow * kStr16 + ahalf * 4];                \
            uint32_t* dL = &Al[st][arow * kStr16 + ahalf * 4];                \
            *reinterpret_cast<uint4*>(dH) = make_uint4(hw[0],hw[1],hw[2],hw[3]); \
            *reinterpret_cast<uint4*>(dL) = make_uint4(lw[0],lw[1],lw[2],lw[3]); \
        }
    #define M3_LOAD_B(k0)                                                     \
        {                                                                     \
            const float* p = B + (size_t)((k0) + ahalf * 8) * ldb + n0 + arow;\
            _Pragma("unroll")                                                 \
            for (int j = 0; j < 8; ++j) bv[j] = p[(size_t)j * ldb];           \
        }
    #define M3_STORE_B(st)                                                    \
        {                                                                     \
            uint32_t hw[4], lw[4];                                            \
            _Pragma("unroll")                                                 \
            for (int j = 0; j < 4; ++j)                                       \
                split_bf16(bv[2*j], bv[2*j+1], hw[j], lw[j]);                 \
            uint32_t* dH = &Bh[st][arow * kStr16 + ahalf * 4];                \
            uint32_t* dL = &Bl[st][arow * kStr16 + ahalf * 4];                \
            *reinterpret_cast<uint4*>(dH) = make_uint4(hw[0],hw[1],hw[2],hw[3]); \
            *reinterpret_cast<uint4*>(dL) = make_uint4(lw[0],lw[1],lw[2],lw[3]); \
        }
    #define M3_COMPUTE(st)                                                    \
        {                                                                     \
            uint32_t ah[4][4], al[4][4], bh[4][2], bl[4][2];                  \
            _Pragma("unroll")                                                 \
            for (int mi = 0; mi < 4; ++mi) {                                  \
                uint32_t woff = (uint32_t)((st) * kArrW16) + aoff +           \
                                (uint32_t)(mi * 16 * kStr16);                 \
                LDM4(ah[mi][0], ah[mi][1], ah[mi][2], ah[mi][3],              \
                     sbAh + woff * 4)                                         \
                LDM4(al[mi][0], al[mi][1], al[mi][2], al[mi][3],              \
                     sbAl + woff * 4)                                         \
            }                                                                 \
            _Pragma("unroll")                                                 \
            for (int nip = 0; nip < 2; ++nip) {                               \
                uint32_t woff = (uint32_t)((st) * kArrW16) + boff +           \
                                (uint32_t)(nip * 16 * kStr16);                \
                LDM4(bh[2*nip][0], bh[2*nip][1], bh[2*nip+1][0],              \
                     bh[2*nip+1][1], sbBh + woff * 4)                         \
                LDM4(bl[2*nip][0], bl[2*nip][1], bl[2*nip+1][0],              \
                     bl[2*nip+1][1], sbBl + woff * 4)                         \
            }                                                                 \
            _Pragma("unroll")                                                 \
            for (int mi = 0; mi < 4; ++mi)                                    \
                _Pragma("unroll")                                             \
                for (int ni = 0; ni < 4; ++ni) {                              \
                    mma_bf16(acc[mi][ni], al[mi], bh[ni]);                    \
                    mma_bf16(acc[mi][ni], ah[mi], bl[ni]);                    \
                    mma_bf16(acc[mi][ni], ah[mi], bh[ni]);                    \
                }                                                             \
        }

    M3_LOAD_A(0)
    M3_LOAD_B(0)
    M3_STORE_A(0)
    M3_STORE_B(0)
    __syncthreads();

    const int nk = K >> 4;
    for (int kt = 0; kt < nk; kt += 2) {
        {
            const bool more = (kt + 1) < nk;
            if (more) {
                const int k0 = (kt + 1) << 4;
                M3_LOAD_A(k0)
                M3_LOAD_B(k0)
            }
            M3_COMPUTE(0)
            if (more) {
                M3_STORE_A(1)
                M3_STORE_B(1)
                __syncthreads();
            }
        }
        if (kt + 1 < nk) {
            const bool more = (kt + 2) < nk;
            if (more) {
                const int k0 = (kt + 2) << 4;
                M3_LOAD_A(k0)
                M3_LOAD_B(k0)
            }
            M3_COMPUTE(1)
            if (more) {
                M3_STORE_A(0)
                M3_STORE_B(0)
                __syncthreads();
            }
        }
    }

    #undef M3_LOAD_A
    #undef M3_STORE_A
    #undef M3_LOAD_B
    #undef M3_STORE_B
    #undef M3_COMPUTE

    #pragma unroll
    for (int mi = 0; mi < 4; ++mi) {
        const int r0 = m0 + wm + mi * 16 + lg;
        #pragma unroll
        for (int ni = 0; ni < 4; ++ni) {
            const int n = n0 + wn + ni * 8 + 2 * lt;
            if (r0 < effM) {
                float2 v = make_float2(acc[mi][ni][0], acc[mi][ni][1]);
                *reinterpret_cast<float2*>(&C[(size_t)r0 * ldc + n]) = v;
            }
            if (r0 + 8 < effM) {
                float2 v = make_float2(acc[mi][ni][2], acc[mi][ni][3]);
                *reinterpret_cast<float2*>(&C[(size_t)(r0 + 8) * ldc + n]) = v;
            }
        }
    }
}

// ---------------------------------------------------------------------------
// Exact fp32 SGEMM (gate logits only: feeds discrete top-k routing).
// ---------------------------------------------------------------------------
template <bool TB>
__global__ void __launch_bounds__(256)
sgemm_kernel(const float* __restrict__ A, const float* __restrict__ B,
             float* __restrict__ C, int M, int N, int K,
             int lda, int ldb, int ldc,
             long long sA, long long sB, long long sC,
             const int* __restrict__ mlim, int causal)
{
    const int bz = blockIdx.z;
    A += (size_t)bz * (size_t)sA;
    B += (size_t)bz * (size_t)sB;
    C += (size_t)bz * (size_t)sC;

    int effM = M;
    if (mlim) { int c = mlim[bz]; if (c < effM) effM = c; }

    const int m0 = blockIdx.y * 128;
    const int n0 = blockIdx.x * 128;
    if (m0 >= effM) return;
    if (causal && n0 > m0 + 127) return;

    __shared__ __align__(16) float As[8][128];
    __shared__ __align__(16) float Bs[8][128];

    const int tid  = threadIdx.x;
    const int rowL = tid >> 1;
    const int kL   = (tid & 1) * 4;
    const int kB   = tid >> 5;
    const int nb   = tid & 31;
    const int ty   = tid >> 4, tx = tid & 15;

    float acc[8][8];
    #pragma unroll
    for (int i = 0; i < 8; ++i)
        #pragma unroll
        for (int j = 0; j < 8; ++j) acc[i][j] = 0.f;

    float ra[4], rb[4];

    {
        #pragma unroll
        for (int i = 0; i < 4; ++i) {
            int m = m0 + rowL, k = kL + i;
            ra[i] = (m < effM && k < K) ? A[(size_t)m * lda + k] : 0.f;
        }
        if (TB) {
            #pragma unroll
            for (int i = 0; i < 4; ++i) {
                int n = n0 + rowL, k = kL + i;
                rb[i] = (n < N && k < K) ? B[(size_t)n * ldb + k] : 0.f;
            }
        } else {
            #pragma unroll
            for (int i = 0; i < 4; ++i) {
                int n = n0 + nb + 32 * i;
                rb[i] = (n < N && kB < K) ? B[(size_t)kB * ldb + n] : 0.f;
            }
        }
        #pragma unroll
        for (int i = 0; i < 4; ++i) As[kL + i][rowL] = ra[i];
        if (TB) {
            #pragma unroll
            for (int i = 0; i < 4; ++i) Bs[kL + i][rowL] = rb[i];
        } else {
            #pragma unroll
            for (int i = 0; i < 4; ++i) Bs[kB][nb + 32 * i] = rb[i];
        }
    }
    __syncthreads();

    const int nk = (K + 7) >> 3;
    for (int kt = 0; kt < nk; ++kt) {
        const bool more = (kt + 1) < nk;
        const int k0 = (kt + 1) << 3;
        if (more) {
            #pragma unroll
            for (int i = 0; i < 4; ++i) {
                int m = m0 + rowL, k = k0 + kL + i;
                ra[i] = (m < effM && k < K) ? A[(size_t)m * lda + k] : 0.f;
            }
            if (TB) {
                #pragma unroll
                for (int i = 0; i < 4; ++i) {
                    int n = n0 + rowL, k = k0 + kL + i;
                    rb[i] = (n < N && k < K) ? B[(size_t)n * ldb + k] : 0.f;
                }
            } else {
                #pragma unroll
                for (int i = 0; i < 4; ++i) {
                    int n = n0 + nb + 32 * i, k = k0 + kB;
                    rb[i] = (n < N && k < K) ? B[(size_t)k * ldb + n] : 0.f;
                }
            }
        }
        #pragma unroll
        for (int kk = 0; kk < 8; ++kk) {
            float a[8], b[8];
            *reinterpret_cast<float4*>(&a[0]) = *reinterpret_cast<const float4*>(&As[kk][ty * 8]);
            *reinterpret_cast<float4*>(&a[4]) = *reinterpret_cast<const float4*>(&As[kk][ty * 8 + 4]);
            *reinterpret_cast<float4*>(&b[0]) = *reinterpret_cast<const float4*>(&Bs[kk][tx * 8]);
            *reinterpret_cast<float4*>(&b[4]) = *reinterpret_cast<const float4*>(&Bs[kk][tx * 8 + 4]);
            #pragma unroll
            for (int i = 0; i < 8; ++i)
                #pragma unroll
                for (int j = 0; j < 8; ++j)
                    acc[i][j] = fmaf(a[i], b[j], acc[i][j]);
        }
        __syncthreads();
        if (more) {
            #pragma unroll
            for (int i = 0; i < 4; ++i) As[kL + i][rowL] = ra[i];
            if (TB) {
                #pragma unroll
                for (int i = 0; i < 4; ++i) Bs[kL + i][rowL] = rb[i];
            } else {
                #pragma unroll
                for (int i = 0; i < 4; ++i) Bs[kB][nb + 32 * i] = rb[i];
            }
            __syncthreads();
        }
    }

    #pragma unroll
    for (int i = 0; i < 8; ++i) {
        int m = m0 + ty * 8 + i;
        if (m >= effM) continue;
        #pragma unroll
        for (int j = 0; j < 8; ++j) {
            int n = n0 + tx * 8 + j;
            if (n < N) C[(size_t)m * ldc + n] = acc[i][j];
        }
    }
}

// ---------------------------------------------------------------------------
// RMSNorm over rows of [*, HID]
// ---------------------------------------------------------------------------
__global__ void rmsnorm_kernel(const float* __restrict__ x,
                               const float* __restrict__ w,
                               float* __restrict__ y)
{
    const int t = blockIdx.x, tid = threadIdx.x;
    const float* xr = x + (size_t)t * kHID;
    float s = 0.f;
    for (int i = tid; i < kHID; i += 256) { float v = xr[i]; s += v * v; }
    __shared__ float red[256];
    red[tid] = s; __syncthreads();
    for (int st = 128; st > 0; st >>= 1) {
        if (tid < st) red[tid] += red[tid + st];
        __syncthreads();
    }
    const float sc = rsqrtf(red[0] / (float)kHID + kEPS);
    for (int i = tid; i < kHID; i += 256)
        y[(size_t)t * kHID + i] = xr[i] * sc * w[i];
}

// ---------------------------------------------------------------------------
// Fused q/k rmsnorm + rope + GQA replication + v replication.
// ---------------------------------------------------------------------------
__global__ void rope_kernel(const float* __restrict__ qbuf,
                            const float* __restrict__ kbuf,
                            const float* __restrict__ vbuf,
                            const int* __restrict__ pos,
                            const float* __restrict__ qw,
                            const float* __restrict__ kw,
                            float* __restrict__ qh,
                            float* __restrict__ krep,
                            float* __restrict__ vrep)
{
    const int t = blockIdx.x, y = blockIdx.y, d = threadIdx.x;
    constexpr int kRep = kNH / kNKV;
    constexpr float kNegLog2Theta = -19.931568569324174f / 64.0f;

    if (y >= 36) {
        const int kv = y - 36;
        float v = vbuf[(size_t)t * (kNKV * kHD) + kv * kHD + d];
        #pragma unroll
        for (int r = 0; r < kRep; ++r)
            vrep[((size_t)(kv * kRep + r) * kT + t) * kHD + d] = v;
        return;
    }

    const bool isq = (y < 32);
    const float* src = isq ? (qbuf + (size_t)t * (kNH * kHD) + y * kHD)
                           : (kbuf + (size_t)t * (kNKV * kHD) + (y - 32) * kHD);
    const float* w = isq ? qw : kw;

    float v = src[d];
    __shared__ float red[kHD];
    red[d] = v * v;
    __syncthreads();
    #pragma unroll
    for (int s = 64; s > 0; s >>= 1) {
        if (d < s) red[d] += red[d + s];
        __syncthreads();
    }
    const float sc = rsqrtf(red[0] / (float)kHD + kEPS);
    __syncthreads();
    red[d] = v * sc * w[d];
    __syncthreads();

    const int j = (d < 64) ? d : d - 64;
    const float f = (float)pos[t] * exp2f((float)j * kNegLog2Theta);
    float cs, sn;
    sincosf(f, &sn, &cs);
    const float o = (d < 64) ? (red[d] * cs - red[d + 64] * sn)
                             : (red[d - 64] * sn + red[d] * cs);

    if (isq) {
        qh[((size_t)y * kT + t) * kHD + d] = o;
    } else {
        const int kv = y - 32;
        #pragma unroll
        for (int r = 0; r < kRep; ++r)
            krep[((size_t)(kv * kRep + r) * kT + t) * kHD + d] = o;
    }
}

// ---------------------------------------------------------------------------
// Causal row softmax (fast __expf). Zero-fills only to the 128-aligned
// block end.
// ---------------------------------------------------------------------------
__global__ void softmax_kernel(float* __restrict__ sc)
{
    const int h = blockIdx.x, q = blockIdx.y, tid = threadIdx.x;
    float* row = sc + ((size_t)h * kT + q) * kT;
    const int len = q + 1;
    const int fill = ((q >> 7) + 1) << 7;
    const float scale = 0.08838834764831845f;

    __shared__ float red[256];
    float m = -1e30f;
    for (int i = tid; i < len; i += 256) m = fmaxf(m, row[i]);
    red[tid] = m; __syncthreads();
    for (int st = 128; st > 0; st >>= 1) {
        if (tid < st) red[tid] = fmaxf(red[tid], red[tid + st]);
        __syncthreads();
    }
    m = red[0] * scale;
    __syncthreads();

    float s = 0.f;
    for (int i = tid; i < len; i += 256) s += __expf(row[i] * scale - m);
    red[tid] = s; __syncthreads();
    for (int st = 128; st > 0; st >>= 1) {
        if (tid < st) red[tid] += red[tid + st];
        __syncthreads();
    }
    const float inv = 1.f / red[0];

    for (int i = tid; i < fill; i += 256) {
        float v = (i < len) ? __expf(row[i] * scale - m) * inv : 0.f;
        row[i] = v;
    }
}

// ---------------------------------------------------------------------------
// Capacity-aware SiLU (vectorized float4, fast __expf): one block per
// (expert, cap-row); skips unrouted rows.
// ---------------------------------------------------------------------------
__global__ void silu_kernel(float* __restrict__ g, const float* __restrict__ u,
                            const int* __restrict__ cnt)
{
    const int b = blockIdx.x;
    const int e = b >> 8, r = b & (kCAP - 1);
    if (r >= cnt[e]) return;
    float4* gr = reinterpret_cast<float4*>(g + (size_t)b * kI);
    const float4* ur = reinterpret_cast<const float4*>(u + (size_t)b * kI);
    for (int i = threadIdx.x; i < kI / 4; i += blockDim.x) {
        float4 x = gr[i];
        float4 y = ur[i];
        x.x = x.x / (1.f + __expf(-x.x)) * y.x;
        x.y = x.y / (1.f + __expf(-x.y)) * y.y;
        x.z = x.z / (1.f + __expf(-x.z)) * y.z;
        x.w = x.w / (1.f + __expf(-x.w)) * y.w;
        gr[i] = x;
    }
}

// ---------------------------------------------------------------------------
// Gate softmax + top-8 (exact expf — feeds discrete routing)
// ---------------------------------------------------------------------------
__global__ void topk_kernel(const float* __restrict__ logits,
                            float* __restrict__ topw, int* __restrict__ topi)
{
    const int t = blockIdx.x, lane = threadIdx.x;
    float l0 = logits[t * kE + lane];
    float l1 = logits[t * kE + 32 + lane];
    float m = fmaxf(l0, l1);
    for (int off = 16; off; off >>= 1) m = fmaxf(m, __shfl_xor_sync(0xffffffffu, m, off));
    float e0 = expf(l0 - m), e1 = expf(l1 - m);
    float s = e0 + e1;
    for (int off = 16; off; off >>= 1) s += __shfl_xor_sync(0xffffffffu, s, off);
    float p0 = e0 / s, p1 = e1 / s;

    float sel[kK]; int seli[kK];
    #pragma unroll
    for (int k = 0; k < kK; ++k) {
        float v = p0; int idx = lane;
        if (p1 > v) { v = p1; idx = lane + 32; }
        for (int off = 16; off; off >>= 1) {
            float ov = __shfl_xor_sync(0xffffffffu, v, off);
            int   oi = __shfl_xor_sync(0xffffffffu, idx, off);
            if (ov > v || (ov == v && oi < idx)) { v = ov; idx = oi; }
        }
        sel[k] = v; seli[k] = idx;
        if (idx == lane)      p0 = -1.f;
        if (idx == lane + 32) p1 = -1.f;
    }
    if (lane == 0) {
        float sum = 0.f;
        #pragma unroll
        for (int k = 0; k < kK; ++k) sum += sel[k];
        #pragma unroll
        for (int k = 0; k < kK; ++k) {
            topw[t * kK + k] = sel[k] / sum;
            topi[t * kK + k] = seli[k];
        }
    }
}

// ---------------------------------------------------------------------------
// Routing: stable (t,k)-order ranks per expert, capacity drop.
// ---------------------------------------------------------------------------
__global__ void route_kernel(const int* __restrict__ topi,
                             int* __restrict__ tok, int* __restrict__ slot,
                             int* __restrict__ cnt)
{
    const int e = blockIdx.x, tid = threadIdx.x;
    constexpr int A = kT * kK;
    constexpr int PER = A / 256;
    int c = 0;
    for (int i = 0; i < PER; ++i) c += (topi[tid * PER + i] == e);

    __shared__ int s[256];
    s[tid] = c; __syncthreads();
    for (int off = 1; off < 256; off <<= 1) {
        int v = (tid >= off) ? s[tid - off] : 0;
        __syncthreads();
        s[tid] += v;
        __syncthreads();
    }
    const int total = s[255];
    int r = s[tid] - c;

    for (int i = 0; i < PER; ++i) {
        int a = tid * PER + i;
        if (topi[a] == e) {
            if (r < kCAP) {
                tok[e * kCAP + r] = a / kK;
                slot[a] = e * kCAP + r;
            } else {
                slot[a] = -1;
            }
            ++r;
        }
    }
    if (tid == 0) cnt[e] = (total < kCAP) ? total : kCAP;
}

__global__ void gather_kernel(const float* __restrict__ h2,
                              const int* __restrict__ tok,
                              const int* __restrict__ cnt,
                              float* __restrict__ xb)
{
    const int b = blockIdx.x;
    const int e = b >> 8, r = b & (kCAP - 1);
    if (r >= cnt[e]) return;
    const int t = tok[b];
    const float4* src = reinterpret_cast<const float4*>(h2 + (size_t)t * kHID);
    float4* dst = reinterpret_cast<float4*>(xb + (size_t)b * kHID);
    for (int i = threadIdx.x; i < kHID / 4; i += blockDim.x) dst[i] = src[i];
}

__global__ void combine_kernel(const float* __restrict__ yb,
                               const int* __restrict__ slot,
                               const float* __restrict__ topw,
                               float* __restrict__ out)
{
    const int t = blockIdx.x;
    __shared__ int ss[kK];
    __shared__ float sw[kK];
    if (threadIdx.x < kK) {
        ss[threadIdx.x] = slot[t * kK + threadIdx.x];
        sw[threadIdx.x] = topw[t * kK + threadIdx.x];
    }
    __syncthreads();
    for (int c = threadIdx.x; c < kHID; c += blockDim.x) {
        float acc = 0.f;
        #pragma unroll
        for (int k = 0; k < kK; ++k) {
            int sl = ss[k];
            if (sl >= 0) acc += sw[k] * yb[(size_t)sl * kHID + c];
        }
        out[(size_t)t * kHID + c] = acc;
    }
}

// ---------------------------------------------------------------------------
// Launcher
// ---------------------------------------------------------------------------
extern "C" void kernel_launch(void* const* d_in, const int* in_sizes, int n_in,
                              void* d_out, int out_size)
{
    const float* hidden    = (const float*)d_in[0];
    const int*   pos       = (const int*)  d_in[1];
    const float* ln_in_w   = (const float*)d_in[2];
    const float* ln_post_w = (const float*)d_in[3];
    const float* q_norm_w  = (const float*)d_in[4];
    const float* k_norm_w  = (const float*)d_in[5];
    const float* wq        = (const float*)d_in[6];
    const float* wk        = (const float*)d_in[7];
    const float* wv        = (const float*)d_in[8];
    const float* wo        = (const float*)d_in[9];
    const float* gate_w    = (const float*)d_in[10];
    const float* we_gate   = (const float*)d_in[11];
    const float* we_up     = (const float*)d_in[12];
    const float* we_down   = (const float*)d_in[13];

    float* out   = (float*)d_out;
    float* resid = out + (size_t)kT * kHID;

    float *hnorm, *h2, *qbuf, *kbuf, *vbuf, *qh, *krep, *vrep, *attno,
          *scores, *logits, *topw, *xb, *gbuf, *ubuf;
    int *topi, *cnt, *tok, *slot;
    cudaGetSymbolAddress((void**)&hnorm,  g_hnorm);
    cudaGetSymbolAddress((void**)&h2,     g_h2);
    cudaGetSymbolAddress((void**)&qbuf,   g_qbuf);
    cudaGetSymbolAddress((void**)&kbuf,   g_kbuf);
    cudaGetSymbolAddress((void**)&vbuf,   g_vbuf);
    cudaGetSymbolAddress((void**)&qh,     g_qh);
    cudaGetSymbolAddress((void**)&krep,   g_krep);
    cudaGetSymbolAddress((void**)&vrep,   g_vrep);
    cudaGetSymbolAddress((void**)&attno,  g_attno);
    cudaGetSymbolAddress((void**)&scores, g_scores);
    cudaGetSymbolAddress((void**)&logits, g_logits);
    cudaGetSymbolAddress((void**)&topw,   g_topw);
    cudaGetSymbolAddress((void**)&topi,   g_topi);
    cudaGetSymbolAddress((void**)&cnt,    g_cnt);
    cudaGetSymbolAddress((void**)&tok,    g_tok);
    cudaGetSymbolAddress((void**)&slot,   g_slot);
    cudaGetSymbolAddress((void**)&xb,     g_xb);
    cudaGetSymbolAddress((void**)&gbuf,   g_gbuf);
    cudaGetSymbolAddress((void**)&ubuf,   g_ubuf);

    // Opt-in to 80KB dynamic smem for BK=32 kernels (host-side only).
    static bool attr_done = false;
    if (!attr_done) {
        cudaFuncSetAttribute(qkv_kernel,
                             cudaFuncAttributeMaxDynamicSharedMemorySize, kB32Smem);
        cudaFuncSetAttribute(bgemm3_kernel<false>,
                             cudaFuncAttributeMaxDynamicSharedMemorySize, kB32Smem);
        cudaFuncSetAttribute(bgemm3_kernel<true>,
                             cudaFuncAttributeMaxDynamicSharedMemorySize, kB32Smem);
        attr_done = true;
    }

    // 1) input RMSNorm
    rmsnorm_kernel<<<kT, 256>>>(hidden, ln_in_w, hnorm);

    // 2) fused Q/K/V projections (ldmatrix BK=32, gather NN stores)
    qkv_kernel<<<dim3(40, kT / 128, 1), 256, kB32Smem>>>(
        hnorm, wq, wk, wv, qbuf, kbuf, vbuf);

    // 3) fused q/k rmsnorm + rope (+ GQA replication) + v replication
    rope_kernel<<<dim3(kT, 40), kHD>>>(
        qbuf, kbuf, vbuf, pos, q_norm_w, k_norm_w, qh, krep, vrep);

    // 4) S = Q @ K^T (causal block skip)
    bgemm3_kernel<true><<<dim3(kT / 128, kT / 128, kNH), 256, kB32Smem>>>(
        qh, krep, scores, kT, kT, kHD, kHD, kHD, kT,
        (long long)kT * kHD, (long long)kT * kHD, (long long)kT * kT,
        nullptr, 1, nullptr);

    // 5) causal softmax (block-limited fill, fast exp)
    softmax_kernel<<<dim3(kNH, kT), 256>>>(scores);

    // 6) O = P @ V (causal K-truncation)
    bgemm3_kernel<false><<<dim3(1, kT / 128, kNH), 256, kB32Smem>>>(
        scores, vrep, attno, kT, kHD, kT, kT, kHD, kNH * kHD,
        (long long)kT * kT, (long long)kT * kHD, (long long)kHD,
        nullptr, 2, nullptr);

    // 7) output projection with fused residual add -> resid
    bgemm3_kernel<false><<<dim3(kHID / 128, kT / 128, 1), 256, kB32Smem>>>(
        attno, wo, resid, kT, kHID, kNH * kHD, kNH * kHD, kHID, kHID,
        0, 0, 0, nullptr, 0, hidden);

    // 8) post-attention RMSNorm
    rmsnorm_kernel<<<kT, 256>>>(resid, ln_post_w, h2);

    // 9) gate logits (exact fp32) + top-k + routing
    sgemm_kernel<false><<<dim3(1, kT / 128, 1), 256>>>(
        h2, gate_w, logits, kT, kE, kHID, kHID, kE, kE, 0, 0, 0, nullptr, 0);
    topk_kernel <<<kT, 32>>>(logits, topw, topi);
    route_kernel<<<kE, 256>>>(topi, tok, slot, cnt);
    gather_kernel<<<kE * kCAP, 256>>>(h2, tok, cnt, xb);

    // 10) expert FFN (R14-proven: plain moe3 + separate capacity-aware silu)
    moe3_kernel<<<dim3(kI / 128, kCAP / 128, kE), 256>>>(
        xb, we_gate, gbuf, kCAP, kI, kHID, kHID, kI, kI,
        (long long)kCAP * kHID, (long long)kHID * kI, (long long)kCAP * kI,
        cnt);
    moe3_kernel<<<dim3(kI / 128, kCAP / 128, kE), 256>>>(
        xb, we_up, ubuf, kCAP, kI, kHID, kHID, kI, kI,
        (long long)kCAP * kHID, (long long)kHID * kI, (long long)kCAP * kI,
        cnt);
    silu_kernel<<<kE * kCAP, 192>>>(gbuf, ubuf, cnt);
    moe3_kernel<<<dim3(kHID / 128, kCAP / 128, kE), 256>>>(
        gbuf, we_down, xb, kCAP, kHID, kI, kI, kHID, kHID,
        (long long)kCAP * kI, (long long)kI * kHID, (long long)kCAP * kHID,
        cnt);

    // 11) weighted combine -> out
    combine_kernel<<<kT, 256>>>(xb, slot, topw, out);
}